// round 16
// baseline (speedup 1.0000x reference)
#include <cuda_runtime.h>

#define BB 32
#define TT 512
#define UU 512
#define NG 1536          // 3*U
#define OC 1024          // 2*U output channels

// per-step rh = r * h_prev exchange buffer
__device__ float    g_rh[2 * BB * UU];
// per-step split barriers (reset at kernel end, replay-safe)
__device__ int      g_bar1[2 * TT];
__device__ int      g_bar2[2 * TT];
__device__ int      g_done;

__device__ __forceinline__ float hsig(float v) {
    return fminf(fmaxf(0.2f * v + 0.5f, 0.0f), 1.0f);
}

// consumer-only named barrier (warps 8-15, 256 threads)
#define BAR_CONS() asm volatile("bar.sync 1, 256;" ::: "memory")

// ---------------------------------------------------------------------------
// Fused persistent kernel. 128 blocks x 512 threads (1 block/SM).
//   warps 0-7  (tid 0..255)  : PRODUCERS (low wid = low arbiter priority) —
//       x-gate projection for this block's 24 gate-cols, weights in REGISTERS,
//       warp-shuffle reduction. ~2.2K warp-instr/step, ~0 crossbar.
//   warps 8-15 (tid 256..511): CONSUMERS (high wid = priority) — exact r14
//       GRU scan: split A-r/A-z bar1 hiding + grid barriers.
// Handoff: one full-block __syncthreads per step (xbuf ring phase flip).
// smem floats: sW 12288 | sH 16416 | red 2048 | xbuf 1536 = 32288 (129,152 B)
// ---------------------------------------------------------------------------
#define SCAN_SMEM_FLOATS (12288 + 16416 + 2048 + 1536)
#define SCAN_SMEM_BYTES  (SCAN_SMEM_FLOATS * 4)

__global__ void __launch_bounds__(512, 1)
scan_kernel(const float* __restrict__ x,
            const float* __restrict__ Wf, const float* __restrict__ Uf,
            const float* __restrict__ bf,
            const float* __restrict__ Wb, const float* __restrict__ Ub,
            const float* __restrict__ bb,
            float* __restrict__ out)
{
    extern __shared__ float sm[];
    float* sW   = sm;              // recurrent U slice [g][u][c] : g*4096+u*8+c
    float* sH   = sm + 12288;      // h staging [b][u] : b*513 + u
    float* red  = sH + 16416;      // reduction scratch (4 ks x 32 b x 8 c)
    float* xbuf = red + 2048;      // ring: ph*768 + g*256 + b*8 + c

    const int tid   = threadIdx.x;
    const int dir   = blockIdx.x >> 6;
    const int cg    = blockIdx.x & 63;
    const int hbase = cg << 3;
    const float* __restrict__ Urec = dir ? Ub : Uf;
    const float* __restrict__ Win  = dir ? Wb : Wf;
    const float* __restrict__ bias = dir ? bb : bf;

    int* __restrict__ bar1 = g_bar1 + dir * TT;
    int* __restrict__ bar2 = g_bar2 + dir * TT;
    const int rh_base = (dir * BB) << 9;

    if (tid < 256) {
        // =================== PRODUCER WARPS (0..7, low priority) ==========
        const int pks = tid & 31;          // K-slice lane (coalesced x reads)
        const int pc  = tid >> 5;          // 0..7 column
        const int u0p = pks << 4;          // 16 K-values per thread

        // input weights in REGISTERS, loaded once
        float wzr[16], wrr[16], whr[16];
#pragma unroll
        for (int k = 0; k < 16; ++k) {
            const size_t row = (size_t)(u0p + k) * NG;
            wzr[k] = Win[row + hbase + pc];
            wrr[k] = Win[row + UU + hbase + pc];
            whr[k] = Win[row + 2 * UU + hbase + pc];
        }
        const float bz = bias[hbase + pc];
        const float br = bias[UU + hbase + pc];
        const float bh = bias[2 * UU + hbase + pc];

        // produce x-gate tile for step sp into xbuf[sp&1]
        auto produce = [&](int sp) {
            const int t_x = dir ? (TT - 1 - sp) : sp;
            float* dst = xbuf + (sp & 1) * 768;
            for (int bb2 = 0; bb2 < 32; ++bb2) {
                const float4* __restrict__ xr4 =
                    (const float4*)(x + ((size_t)bb2 * TT + t_x) * UU + u0p);
                float az = 0.f, ar = 0.f, ah = 0.f;
#pragma unroll
                for (int q = 0; q < 4; ++q) {
                    const float4 xv = __ldg(xr4 + q);
                    const int k = q << 2;
                    az = fmaf(xv.x, wzr[k],     az);
                    ar = fmaf(xv.x, wrr[k],     ar);
                    ah = fmaf(xv.x, whr[k],     ah);
                    az = fmaf(xv.y, wzr[k + 1], az);
                    ar = fmaf(xv.y, wrr[k + 1], ar);
                    ah = fmaf(xv.y, whr[k + 1], ah);
                    az = fmaf(xv.z, wzr[k + 2], az);
                    ar = fmaf(xv.z, wrr[k + 2], ar);
                    ah = fmaf(xv.z, whr[k + 2], ah);
                    az = fmaf(xv.w, wzr[k + 3], az);
                    ar = fmaf(xv.w, wrr[k + 3], ar);
                    ah = fmaf(xv.w, whr[k + 3], ah);
                }
                // butterfly reduce across the 32 K-slice lanes
#pragma unroll
                for (int off = 16; off; off >>= 1) {
                    az += __shfl_xor_sync(0xffffffffu, az, off);
                    ar += __shfl_xor_sync(0xffffffffu, ar, off);
                    ah += __shfl_xor_sync(0xffffffffu, ah, off);
                }
                if (pks == 0) {
                    dst[bb2 * 8 + pc]       = az + bz;
                    dst[256 + bb2 * 8 + pc] = ar + br;
                    dst[512 + bb2 * 8 + pc] = ah + bh;
                }
            }
        };

        produce(0);                        // prime tile 0
        __syncthreads();                   // init handoff

        for (int s = 0; s < TT; ++s) {
            if (s + 1 < TT) produce(s + 1);
            __syncthreads();               // end-of-step handoff
        }
    } else {
        // =================== CONSUMER WARPS (8..15, high priority) ========
        const int ct = tid - 256;          // 0..255

        // recurrent weight slice: sW[g][u][c] = Urec[u][g*512 + hbase + c]
#pragma unroll 4
        for (int i = ct; i < 12288; i += 256) {
            const int c = i & 7;
            const int u = (i >> 3) & 511;
            const int g = i >> 12;
            sW[i] = Urec[(size_t)u * NG + g * UU + hbase + c];
        }

        // GEMM mapping (r12/r14): 4 ks x 8 bg x 8 c
        const int ks = ct >> 6;            // 0..3 (K quarter)
        const int bg = (ct >> 3) & 7;      // 0..7 (batch group of 4)
        const int c  = ct & 7;             // 0..7
        const int u0 = ks << 7;
        // reduce mapping
        const int rb = ct >> 3;            // 0..31
        const int rc = ct & 7;             // 0..7
        const int j  = hbase + rc;

        const float* __restrict__ pw = sW + (u0 << 3) + c;
        const float* __restrict__ h0 = sH + (bg * 4 + 0) * 513 + u0;
        const float* __restrict__ h1 = h0 + 513;
        const float* __restrict__ h2 = h1 + 513;
        const float* __restrict__ h3 = h2 + 513;

        __syncthreads();                   // init handoff

        for (int s = 0; s < TT; ++s) {
            // x-gate values from smem ring (produced during step s-1)
            const float* xb = xbuf + (s & 1) * 768 + rb * 8 + rc;
            const float xz = xb[0];
            const float xr = xb[256];
            const float xh = xb[512];

            // ---- stage h_prev into sH ----
            if (s == 0) {
                for (int i = ct; i < 16416; i += 256) sH[i] = 0.0f;
            } else {
                const float* __restrict__ hp_base =
                    out + (size_t)(s - 1) * OC + (size_t)dir * UU;
#pragma unroll 4
                for (int i = ct; i < 4096; i += 256) {
                    const int b  = i >> 7;
                    const int u4 = (i & 127) << 2;
                    float4 v = __ldcg((const float4*)(hp_base +
                                      (size_t)b * TT * OC + u4));
                    float* d = sH + b * 513 + u4;
                    d[0] = v.x; d[1] = v.y; d[2] = v.z; d[3] = v.w;
                }
            }
            BAR_CONS();

            const float hp = sH[rb * 513 + j];

            // ---- phase A-r: r-gate GEMM ----
            float ar0 = 0.f, ar1 = 0.f, ar2 = 0.f, ar3 = 0.f;
#pragma unroll 8
            for (int uu = 0; uu < 128; ++uu) {
                const float wr = pw[uu * 8 + 4096];
                ar0 = fmaf(h0[uu], wr, ar0);
                ar1 = fmaf(h1[uu], wr, ar1);
                ar2 = fmaf(h2[uu], wr, ar2);
                ar3 = fmaf(h3[uu], wr, ar3);
            }
            {
                float* rp = red + ks * 256 + (bg * 4) * 8 + c;
                rp[0]  = ar0;
                rp[8]  = ar1;
                rp[16] = ar2;
                rp[24] = ar3;
            }
            BAR_CONS();
            {
                const float* rr = red + rb * 8 + rc;
                const float hr = rr[0] + rr[256] + rr[512] + rr[768];
                const float r  = hsig(xr + hr);
                __stcg(&g_rh[rh_base + (rb << 9) + j], r * hp);
            }
            // arrive(bar1): rh published
            __threadfence();
            BAR_CONS();
            if (ct == 0) atomicAdd(&bar1[s], 1);

            // ---- phase A-z: z-gate GEMM (overlaps bar1 arrivals) ----
            float az0 = 0.f, az1 = 0.f, az2 = 0.f, az3 = 0.f;
#pragma unroll 8
            for (int uu = 0; uu < 128; ++uu) {
                const float wz = pw[uu * 8];
                az0 = fmaf(h0[uu], wz, az0);
                az1 = fmaf(h1[uu], wz, az1);
                az2 = fmaf(h2[uu], wz, az2);
                az3 = fmaf(h3[uu], wz, az3);
            }
            {
                float* rp = red + ks * 256 + (bg * 4) * 8 + c;
                rp[0]  = az0;
                rp[8]  = az1;
                rp[16] = az2;
                rp[24] = az3;
            }
            BAR_CONS();
            float rz = 0.0f, rzh = 0.0f;
            {
                const float* rr = red + rb * 8 + rc;
                const float hz = rr[0] + rr[256] + rr[512] + rr[768];
                const float z  = hsig(xz + hz);
                rz  = z;
                rzh = z * hp;
            }
            // wait(bar1): nearly free by now
            if (ct == 0) {
                while (*(volatile int*)&bar1[s] < 64) { }
                __threadfence();
            }
            BAR_CONS();

            // ---- stage rh into sH ----
#pragma unroll 4
            for (int i = ct; i < 4096; i += 256) {
                const int b  = i >> 7;
                const int u4 = (i & 127) << 2;
                float4 v = __ldcg((const float4*)(g_rh + rh_base +
                                                  (b << 9) + u4));
                float* d = sH + b * 513 + u4;
                d[0] = v.x; d[1] = v.y; d[2] = v.z; d[3] = v.w;
            }
            BAR_CONS();

            // ---- phase B: candidate GEMM ----
            float ah0 = 0.f, ah1 = 0.f, ah2 = 0.f, ah3 = 0.f;
#pragma unroll 8
            for (int uu = 0; uu < 128; ++uu) {
                const float wh = pw[uu * 8 + 8192];
                ah0 = fmaf(h0[uu], wh, ah0);
                ah1 = fmaf(h1[uu], wh, ah1);
                ah2 = fmaf(h2[uu], wh, ah2);
                ah3 = fmaf(h3[uu], wh, ah3);
            }
            {
                float* rp = red + ks * 256 + (bg * 4) * 8 + c;
                rp[0]  = ah0;
                rp[8]  = ah1;
                rp[16] = ah2;
                rp[24] = ah3;
            }
            BAR_CONS();
            {
                const float* rr = red + rb * 8 + rc;
                const float hh   = rr[0] + rr[256] + rr[512] + rr[768];
                const float cand = tanhf(xh + hh);
                const float hnew = rzh + (1.0f - rz) * cand;
                out[((size_t)rb * TT + s) * OC + (size_t)dir * UU + j] = hnew;
            }

            // ---- step closure (bar2): h_new visible to all blocks ----
            __threadfence();
            BAR_CONS();
            if (ct == 0) atomicAdd(&bar2[s], 1);
            if (ct == 0) {
                while (*(volatile int*)&bar2[s] < 64) { }
                __threadfence();
            }
            BAR_CONS();

            __syncthreads();               // end-of-step handoff (all 512)
        }
    }

    // ---- reset per-step counters for next graph replay ----
    __syncthreads();
    if (tid == 0) atomicAdd(&g_done, 1);
    if (blockIdx.x == 0) {
        if (tid == 0) {
            while (*(volatile int*)&g_done < 128) { }
        }
        __syncthreads();
        for (int i = tid; i < 2 * TT; i += 512) {
            g_bar1[i] = 0;
            g_bar2[i] = 0;
        }
        __threadfence();
        __syncthreads();
        if (tid == 0) g_done = 0;
    }
}

// ---------------------------------------------------------------------------
extern "C" void kernel_launch(void* const* d_in, const int* in_sizes, int n_in,
                              void* d_out, int out_size)
{
    (void)in_sizes; (void)n_in; (void)out_size;
    const float* x  = (const float*)d_in[0];
    const float* Wf = (const float*)d_in[1];
    const float* Uf = (const float*)d_in[2];
    const float* bf = (const float*)d_in[3];
    const float* Wb = (const float*)d_in[4];
    const float* Ub = (const float*)d_in[5];
    const float* bb = (const float*)d_in[6];
    float* out = (float*)d_out;

    cudaFuncSetAttribute(scan_kernel,
                         cudaFuncAttributeMaxDynamicSharedMemorySize,
                         SCAN_SMEM_BYTES);

    scan_kernel<<<128, 512, SCAN_SMEM_BYTES>>>(x, Wf, Uf, bf, Wb, Ub, bb, out);
}

// round 17
// speedup vs baseline: 1.9120x; 1.9120x over previous
#include <cuda_runtime.h>

#define BB 32
#define TT 512
#define UU 512
#define NG 1536          // 3*U
#define OC 1024          // 2*U output channels

// x-gates scratch: [dir][B*T][3U] fp32 (192 MB, static device allocation)
__device__ float    g_xg[(size_t)2 * BB * TT * NG];
// per-step rh = r * h_prev exchange buffer [dir][b][u]
__device__ float    g_rh[2 * BB * UU];
// per-step split barriers, one per (dir,bset) group of 16 blocks
__device__ int      g_bar1[8 * TT];
__device__ int      g_bar2[8 * TT];
__device__ int      g_done;

__device__ __forceinline__ float hsig(float v) {
    return fminf(fmaxf(0.2f * v + 0.5f, 0.0f), 1.0f);
}

// ---------------------------------------------------------------------------
// Phase 1: Xg[dir][m][n] = x[m][:] @ W_dir[:][n] + bias_dir[n]
// (verified winner, unchanged from r12-r14)
// ---------------------------------------------------------------------------
#define XS 132           // padded smem row stride (floats)

__global__ void __launch_bounds__(256, 2)
xgemm_kernel(const float* __restrict__ A,
             const float* __restrict__ Wf, const float* __restrict__ bf,
             const float* __restrict__ Wb, const float* __restrict__ bb)
{
    const int dir = blockIdx.z;
    const float* __restrict__ W    = dir ? Wb : Wf;
    const float* __restrict__ bias = dir ? bb : bf;
    const int m0 = blockIdx.y * 128;
    const int n0 = blockIdx.x * 128;

    __shared__ float As[16 * XS];   // [k][m]
    __shared__ float Bs[16 * XS];   // [k][n]

    const int tid = threadIdx.x;
    const int tx = tid & 15;
    const int ty = tid >> 4;

    const int arow = tid >> 1;
    const int akq  = (tid & 1) << 3;
    const int bk = tid >> 4;
    const int bn = (tid & 15) << 3;

    const float* Aptr = A + (size_t)(m0 + arow) * 512 + akq;
    const float* Wptr = W + (size_t)bk * NG + n0 + bn;

    float acc[8][8];
#pragma unroll
    for (int i = 0; i < 8; ++i)
#pragma unroll
        for (int j = 0; j < 8; ++j) acc[i][j] = 0.0f;

    float4 a0 = *(const float4*)(Aptr + 0);
    float4 a1 = *(const float4*)(Aptr + 4);
    float4 b0 = *(const float4*)(Wptr + 0);
    float4 b1 = *(const float4*)(Wptr + 4);

    {
        float av[8] = {a0.x,a0.y,a0.z,a0.w,a1.x,a1.y,a1.z,a1.w};
#pragma unroll
        for (int j = 0; j < 8; ++j) As[(akq + j) * XS + arow] = av[j];
        *(float4*)&Bs[bk * XS + bn]     = b0;
        *(float4*)&Bs[bk * XS + bn + 4] = b1;
    }
    __syncthreads();

    for (int kt = 0; kt < 32; ++kt) {
        const int k_next = (kt + 1) << 4;
        if (kt < 31) {
            a0 = *(const float4*)(Aptr + k_next + 0);
            a1 = *(const float4*)(Aptr + k_next + 4);
            b0 = *(const float4*)(Wptr + (size_t)k_next * NG + 0);
            b1 = *(const float4*)(Wptr + (size_t)k_next * NG + 4);
        }

#pragma unroll
        for (int kk = 0; kk < 16; ++kk) {
            float4 av0 = *(const float4*)&As[kk * XS + ty * 8];
            float4 av1 = *(const float4*)&As[kk * XS + ty * 8 + 4];
            float4 bv0 = *(const float4*)&Bs[kk * XS + tx * 8];
            float4 bv1 = *(const float4*)&Bs[kk * XS + tx * 8 + 4];
            float aa[8]  = {av0.x,av0.y,av0.z,av0.w,av1.x,av1.y,av1.z,av1.w};
            float bb2[8] = {bv0.x,bv0.y,bv0.z,bv0.w,bv1.x,bv1.y,bv1.z,bv1.w};
#pragma unroll
            for (int i = 0; i < 8; ++i)
#pragma unroll
                for (int j = 0; j < 8; ++j)
                    acc[i][j] = fmaf(aa[i], bb2[j], acc[i][j]);
        }

        if (kt < 31) {
            __syncthreads();
            float av[8] = {a0.x,a0.y,a0.z,a0.w,a1.x,a1.y,a1.z,a1.w};
#pragma unroll
            for (int j = 0; j < 8; ++j) As[(akq + j) * XS + arow] = av[j];
            *(float4*)&Bs[bk * XS + bn]     = b0;
            *(float4*)&Bs[bk * XS + bn + 4] = b1;
            __syncthreads();
        }
    }

    float* __restrict__ Cd = g_xg + (size_t)dir * BB * TT * NG;
    const int nbase = n0 + tx * 8;
    float4 bi0 = *(const float4*)(bias + nbase);
    float4 bi1 = *(const float4*)(bias + nbase + 4);
#pragma unroll
    for (int i = 0; i < 8; ++i) {
        const int m = m0 + ty * 8 + i;
        float4 o0, o1;
        o0.x = acc[i][0] + bi0.x; o0.y = acc[i][1] + bi0.y;
        o0.z = acc[i][2] + bi0.z; o0.w = acc[i][3] + bi0.w;
        o1.x = acc[i][4] + bi1.x; o1.y = acc[i][5] + bi1.y;
        o1.z = acc[i][6] + bi1.z; o1.w = acc[i][7] + bi1.w;
        *(float4*)&Cd[(size_t)m * NG + nbase]     = o0;
        *(float4*)&Cd[(size_t)m * NG + nbase + 4] = o1;
    }
}

// ---------------------------------------------------------------------------
// Split barrier (16 arrivals per group) helpers.
// ---------------------------------------------------------------------------
__device__ __forceinline__ void bar_arrive(int* cnt, int tid)
{
    __threadfence();
    __syncthreads();
    if (tid == 0) atomicAdd(cnt, 1);
}

__device__ __forceinline__ void bar_wait(int* cnt, int tid)
{
    if (tid == 0) {
        while (*(volatile int*)cnt < 16) { }
        __threadfence();
    }
    __syncthreads();
}

// ---------------------------------------------------------------------------
// Phase 2: persistent scan, batch-split ownership.
// 128 blocks x 512 threads (1 block/SM). Block = (dir, bset of 8 batches,
// cg of 32 cols). Barrier group = 16 blocks sharing (dir, bset).
// Thread = (ks 0..7, bq 0..1, c 0..31): 4 batches x 1 col x 64 K per gate.
// r14 split A-r / A-z bar1 hiding preserved.
// smem floats: sW 3*32*513 = 49248 | sH 8*516 = 4128 | red 2048
//            = 55424 floats = 221,696 B
// ---------------------------------------------------------------------------
#define SWS 513
#define SHS 516
#define SCAN_SMEM_FLOATS (3 * 32 * SWS + 8 * SHS + 2048)
#define SCAN_SMEM_BYTES  (SCAN_SMEM_FLOATS * 4)

__global__ void __launch_bounds__(512, 1)
scan_kernel(const float* __restrict__ Uf,
            const float* __restrict__ Ub,
            float* __restrict__ out)
{
    extern __shared__ float sm[];
    float* sW  = sm;                    // [(g*32+c)*513 + u]
    float* sH  = sm + 3 * 32 * SWS;     // [b][u] : b*516 + u  (8 local batches)
    float* red = sH + 8 * SHS;          // [ks][b][c] : ks*256 + b*32 + c

    const int tid   = threadIdx.x;
    const int dir   = blockIdx.x >> 6;
    const int bset  = (blockIdx.x >> 4) & 3;   // batch set (8 batches)
    const int cgp   = blockIdx.x & 15;         // column group (32 cols)
    const int hbase = cgp << 5;
    const int b0g   = bset << 3;               // first global batch
    const float* __restrict__ Urec = dir ? Ub : Uf;

    // --- weight slice, loaded ONCE: sW[(g*32+c)*513+u] = Urec[u][g*512+hbase+c]
    for (int i = tid; i < 3 * 32 * 512; i += 512) {
        const int u  = i & 511;
        const int gc = i >> 9;                 // 0..95 : g*32 + c
        const int g  = gc >> 5;
        const int c  = gc & 31;
        sW[gc * SWS + u] = Urec[(size_t)u * NG + g * UU + hbase + c];
    }

    // GEMM mapping
    const int ks = tid >> 6;            // 0..7 (K eighth)
    const int bq = (tid >> 5) & 1;      // 0..1 (batch quad)
    const int c  = tid & 31;            // 0..31 (column)
    const int u0 = ks << 6;
    // reduce mapping (tid < 256)
    const int rb = tid >> 5;            // 0..7 (local batch)
    const int rc = tid & 31;            // 0..31 (column)
    const int j  = hbase + rc;

    const float* __restrict__ pwz = sW + (c)       * SWS + u0;
    const float* __restrict__ pwr = sW + (32 + c)  * SWS + u0;
    const float* __restrict__ pwh = sW + (64 + c)  * SWS + u0;
    const float* __restrict__ h0 = sH + (bq * 4 + 0) * SHS + u0;
    const float* __restrict__ h1 = h0 + SHS;
    const float* __restrict__ h2 = h1 + SHS;
    const float* __restrict__ h3 = h2 + SHS;

    const int grp = (dir << 2) + bset;
    int* __restrict__ bar1 = g_bar1 + grp * TT;
    int* __restrict__ bar2 = g_bar2 + grp * TT;
    const size_t xg_base = ((size_t)dir * BB + b0g + rb) * TT;
    const int    rh_dir  = (dir * BB) << 9;

    __syncthreads();                     // weights ready

    for (int s = 0; s < TT; ++s) {
        // x-gate prefetch (tid < 256)
        const int t_x = dir ? (TT - 1 - s) : s;
        float xz = 0.f, xr = 0.f, xh = 0.f;
        if (tid < 256) {
            const float* __restrict__ xrow = g_xg + (xg_base + t_x) * NG;
            xz = xrow[j];
            xr = xrow[UU + j];
            xh = xrow[2 * UU + j];
        }

        // ---- stage h_prev (8 local batches x 512 u = 1024 float4) ----
        if (s == 0) {
            for (int i = tid; i < 8 * SHS; i += 512) sH[i] = 0.0f;
        } else {
            const float* __restrict__ hp_base =
                out + (size_t)(s - 1) * OC + (size_t)dir * UU;
#pragma unroll
            for (int i = tid; i < 4096; i += 512) {
                const int b  = i >> 9;                 // 0..7
                const int u4 = (i & 511);              // float index /4? no:
                // i in [0,4096): b = i>>9, u = (i & 511) -- scalar float loads
                // use float4: reinterpret: 1024 float4, 2 per thread
                (void)u4; break;
            }
            // float4 version: 1024 float4, 2 per thread
#pragma unroll
            for (int i = tid; i < 1024; i += 512) {
                const int b  = i >> 7;                 // 0..7
                const int u4 = (i & 127) << 2;
                float4 v = __ldcg((const float4*)(hp_base +
                            (size_t)(b0g + b) * TT * OC + u4));
                float* d = sH + b * SHS + u4;
                d[0] = v.x; d[1] = v.y; d[2] = v.z; d[3] = v.w;
            }
        }
        __syncthreads();

        float hp = 0.0f;
        if (tid < 256) hp = sH[rb * SHS + j];

        // ---- phase A-r: r-gate GEMM (4 b x 1 c x 64 K) ----
        float ar0 = 0.f, ar1 = 0.f, ar2 = 0.f, ar3 = 0.f;
#pragma unroll 8
        for (int uu = 0; uu < 64; ++uu) {
            const float wr = pwr[uu];
            ar0 = fmaf(h0[uu], wr, ar0);
            ar1 = fmaf(h1[uu], wr, ar1);
            ar2 = fmaf(h2[uu], wr, ar2);
            ar3 = fmaf(h3[uu], wr, ar3);
        }
        {
            float* rp = red + ks * 256 + (bq * 4) * 32 + c;
            rp[0]  = ar0;
            rp[32] = ar1;
            rp[64] = ar2;
            rp[96] = ar3;
        }
        __syncthreads();
        if (tid < 256) {
            const float* rr = red + rb * 32 + rc;
            float hr = 0.f;
#pragma unroll
            for (int k = 0; k < 8; ++k) hr += rr[k * 256];
            const float r = hsig(xr + hr);
            __stcg(&g_rh[rh_dir + ((b0g + rb) << 9) + j], r * hp);
        }
        bar_arrive(&bar1[s], tid);       // rh published

        // ---- phase A-z: z-gate GEMM (overlaps bar1 arrivals) ----
        float az0 = 0.f, az1 = 0.f, az2 = 0.f, az3 = 0.f;
#pragma unroll 8
        for (int uu = 0; uu < 64; ++uu) {
            const float wz = pwz[uu];
            az0 = fmaf(h0[uu], wz, az0);
            az1 = fmaf(h1[uu], wz, az1);
            az2 = fmaf(h2[uu], wz, az2);
            az3 = fmaf(h3[uu], wz, az3);
        }
        {
            float* rp = red + ks * 256 + (bq * 4) * 32 + c;
            rp[0]  = az0;
            rp[32] = az1;
            rp[64] = az2;
            rp[96] = az3;
        }
        __syncthreads();
        float rz = 0.0f, rzh = 0.0f;
        if (tid < 256) {
            const float* rr = red + rb * 32 + rc;
            float hz = 0.f;
#pragma unroll
            for (int k = 0; k < 8; ++k) hz += rr[k * 256];
            const float z = hsig(xz + hz);
            rz  = z;
            rzh = z * hp;
        }
        bar_wait(&bar1[s], tid);         // nearly free

        // ---- stage rh (1024 float4, contiguous per batch) ----
#pragma unroll
        for (int i = tid; i < 1024; i += 512) {
            const int b  = i >> 7;
            const int u4 = (i & 127) << 2;
            float4 v = __ldcg((const float4*)(g_rh + rh_dir +
                              ((b0g + b) << 9) + u4));
            float* d = sH + b * SHS + u4;
            d[0] = v.x; d[1] = v.y; d[2] = v.z; d[3] = v.w;
        }
        __syncthreads();

        // ---- phase B: candidate GEMM ----
        float ah0 = 0.f, ah1 = 0.f, ah2 = 0.f, ah3 = 0.f;
#pragma unroll 8
        for (int uu = 0; uu < 64; ++uu) {
            const float wh = pwh[uu];
            ah0 = fmaf(h0[uu], wh, ah0);
            ah1 = fmaf(h1[uu], wh, ah1);
            ah2 = fmaf(h2[uu], wh, ah2);
            ah3 = fmaf(h3[uu], wh, ah3);
        }
        {
            float* rp = red + ks * 256 + (bq * 4) * 32 + c;
            rp[0]  = ah0;
            rp[32] = ah1;
            rp[64] = ah2;
            rp[96] = ah3;
        }
        __syncthreads();
        if (tid < 256) {
            const float* rr = red + rb * 32 + rc;
            float hh = 0.f;
#pragma unroll
            for (int k = 0; k < 8; ++k) hh += rr[k * 256];
            const float cand = tanhf(xh + hh);
            const float hnew = rzh + (1.0f - rz) * cand;
            out[((size_t)(b0g + rb) * TT + s) * OC + (size_t)dir * UU + j] = hnew;
        }

        // ---- step closure ----
        bar_arrive(&bar2[s], tid);
        bar_wait(&bar2[s], tid);
    }

    // ---- reset per-step counters for next graph replay ----
    __syncthreads();
    if (tid == 0) atomicAdd(&g_done, 1);
    if (blockIdx.x == 0) {
        if (tid == 0) {
            while (*(volatile int*)&g_done < 128) { }
        }
        __syncthreads();
        for (int i = tid; i < 8 * TT; i += 512) {
            g_bar1[i] = 0;
            g_bar2[i] = 0;
        }
        __threadfence();
        __syncthreads();
        if (tid == 0) g_done = 0;
    }
}

// ---------------------------------------------------------------------------
extern "C" void kernel_launch(void* const* d_in, const int* in_sizes, int n_in,
                              void* d_out, int out_size)
{
    (void)in_sizes; (void)n_in; (void)out_size;
    const float* x  = (const float*)d_in[0];
    const float* Wf = (const float*)d_in[1];
    const float* Uf = (const float*)d_in[2];
    const float* bf = (const float*)d_in[3];
    const float* Wb = (const float*)d_in[4];
    const float* Ub = (const float*)d_in[5];
    const float* bb = (const float*)d_in[6];
    float* out = (float*)d_out;

    cudaFuncSetAttribute(scan_kernel,
                         cudaFuncAttributeMaxDynamicSharedMemorySize,
                         SCAN_SMEM_BYTES);

    dim3 g1(NG / 128, (BB * TT) / 128, 2);   // 12 x 128 x 2
    xgemm_kernel<<<g1, 256>>>(x, Wf, bf, Wb, bb);

    scan_kernel<<<128, 512, SCAN_SMEM_BYTES>>>(Uf, Ub, out);
}